// round 13
// baseline (speedup 1.0000x reference)
#include <cuda_runtime.h>
#include <math.h>

#define N_ANCH 10647
#define OFF1   8112     // 52*52*3
#define OFF2   10140    // OFF1 + 26*26*3
#define HW0    2704     // 52*52
#define HW1    676      // 26*26
#define HW2    169      // 13*13
#define CONF_T 0.001f
#define NCLS   20
#define CCAP   1024     // per-class capacity (mean ~532, sd ~22.5)
#define SPITCH 33       // smem mask pitch (bank-conflict-free: bank = (i+w) mod 32)

// ---------------- device scratch (static, no allocation) ----------------
__device__ float4             d_boxes[N_ANCH];      // decoded boxes (unclipped, normalized)
__device__ unsigned long long d_ckey [NCLS * CCAP]; // per-class keys (~score<<32 | idx)
__device__ int                d_ccnt [NCLS];        // per-class counts (self-resetting)

// anchors[scale][a][wh], already multiplied by {4,2,1}
__constant__ float c_anch[3][3][2] = {
    {{ 4.f, 6.f},{ 8.f,12.f},{12.f,10.f}},   // stride 8
    {{ 3.f, 7.f},{ 6.f, 8.f},{ 8.f, 6.f}},   // stride 16
    {{3.5f, 5.f},{ 5.f,4.5f},{ 8.f, 8.f}}    // stride 32
};

__device__ __forceinline__ float sigmoidf_(float v) { return 1.f / (1.f + expf(-v)); }

// ---------------- kernel 1: decode batch 0 + class bucketing (coalesced) ----------------
__global__ void k_decode(const float* __restrict__ p0,
                         const float* __restrict__ p1,
                         const float* __restrict__ p2,
                         float* __restrict__ out)
{
    int t = blockIdx.x * blockDim.x + threadIdx.x;
    if (t >= N_ANCH) return;

    // a-major, hw-minor mapping: consecutive threads -> consecutive hw (coalesced loads)
    const float* p; int G, HW, off, sc; float st;
    if (t < OFF1)      { p = p0; G = 52; HW = HW0; off = 0;    sc = 0; st =  8.f; }
    else if (t < OFF2) { p = p1; G = 26; HW = HW1; off = OFF1; sc = 1; st = 16.f; }
    else               { p = p2; G = 13; HW = HW2; off = OFF2; sc = 2; st = 32.f; }

    int rel = t - off;
    int a   = rel / HW;
    int hw  = rel - a * HW;
    int y   = hw / G;
    int x   = hw - y * G;
    int GG  = HW;
    int idx = off + hw * 3 + a;                // original anchor index
    const float* base = p + hw;                // batch 0, channel stride = GG

    float obj = sigmoidf_(base[(size_t)a * GG]);

    float l[NCLS];
    float m = -3.4e38f; int am = 0;
#pragma unroll
    for (int c = 0; c < NCLS; c++) {
        l[c] = base[(size_t)(3 + a * NCLS + c) * GG];
        if (l[c] > m) { m = l[c]; am = c; }
    }
    float s = 0.f;
#pragma unroll
    for (int c = 0; c < NCLS; c++) s += expf(l[c] - m);
    float score = obj * (1.f / s);

    float tx = base[(size_t)(63 + a * 4 + 0) * GG];
    float ty = base[(size_t)(63 + a * 4 + 1) * GG];
    float tw = base[(size_t)(63 + a * 4 + 2) * GG];
    float th = base[(size_t)(63 + a * 4 + 3) * GG];

    float cx = sigmoidf_(tx) + (float)x;
    float cy = sigmoidf_(ty) + (float)y;

    float aw, ah;
    if (hw == GG - 1) { aw = 0.f; ah = 0.f; }  // reference zeroes last hw row
    else { aw = c_anch[sc][a][0]; ah = c_anch[sc][a][1]; }

    float bw = expf(tw) * aw;
    float bh = expf(th) * ah;

    float x1 = (cx - bw * 0.5f) * st / 416.f;
    float y1 = (cy - bh * 0.5f) * st / 416.f;
    float x2 = (cx + bw * 0.5f) * st / 416.f;
    float y2 = (cy + bh * 0.5f) * st / 416.f;

    d_boxes[idx] = make_float4(x1, y1, x2, y2);

    unsigned long long key =
        ((unsigned long long)(~__float_as_uint(score)) << 32) | (unsigned)idx;
    int pos = atomicAdd(&d_ccnt[am], 1);
    if (pos < CCAP) d_ckey[am * CCAP + pos] = key;

    float4 ob;
    ob.x = fminf(fmaxf(x1 * 416.f, 0.f), 415.f) / 416.f;
    ob.y = fminf(fmaxf(y1 * 416.f, 0.f), 415.f) / 416.f;
    ob.z = fminf(fmaxf(x2 * 416.f, 0.f), 415.f) / 416.f;
    ob.w = fminf(fmaxf(y2 * 416.f, 0.f), 415.f) / 416.f;
    *(float4*)(out + (size_t)idx * 4) = ob;
    out[4 * N_ANCH + idx] = score;
    out[5 * N_ANCH + idx] = (float)am;
}

// ---------------- kernel 2: fused per-class sort + in-smem mask build + Jacobi NMS ----------------
// Jacobi fixed-point: K^{t+1} = valid & ~supp(K^t), K^0 = valid. Antitone operator;
// masks strictly upper-triangular -> iterates converge exactly to greedy-NMS keep set.
__global__ void __launch_bounds__(1024) k_cnms(float* __restrict__ out)
{
    extern __shared__ unsigned int dyn[];
    unsigned long long* sk    = (unsigned long long*)dyn;     // CCAP keys    (8 KB)
    float4*             sb    = (float4*)(sk + CCAP);         // CCAP boxes   (16 KB)
    float*              sa    = (float*)(sb + CCAP);          // CCAP areas   (4 KB)
    unsigned int*       smask = (unsigned int*)(sa + CCAP);   // CCAP*SPITCH  (132 KB)
    unsigned long long* sx    = (unsigned long long*)smask;   // sort exchange (aliases smask)
    __shared__ unsigned int validw_s[32], keep_s[32], supp_s[32];
    __shared__ int changed;

    const int c    = blockIdx.x;
    const int tid  = threadIdx.x;
    const int lane = tid & 31;
    const int w    = tid >> 5;                 // warp id == supp word this warp owns

    int nc = d_ccnt[c];
    if (nc > CCAP) nc = CCAP;
    const int nwords = (nc + 31) >> 5;

    // ---- sort (register bitonic; cross-warp stages via aliased smem) ----
    unsigned long long v = (tid < nc) ? d_ckey[c * CCAP + tid] : 0xFFFFFFFFFFFFFFFFULL;
    for (int k = 2; k <= CCAP; k <<= 1) {
        int j = k >> 1;
        for (; j >= 32; j >>= 1) {
            sx[tid] = v;
            __syncthreads();
            unsigned long long o = sx[tid ^ j];
            bool takeMin = (((tid & j) == 0) == ((tid & k) == 0));
            v = takeMin ? (v < o ? v : o) : (v < o ? o : v);
            __syncthreads();
        }
        for (; j > 0; j >>= 1) {
            unsigned long long o = __shfl_xor_sync(0xFFFFFFFFu, v, j);
            bool takeMin = (((lane & j) == 0) == ((tid & k) == 0));
            v = takeMin ? (v < o ? v : o) : (v < o ? o : v);
        }
    }
    __syncthreads();                           // sx reads done before smask reuse
    sk[tid] = v;

    // ---- gather boxes/areas + validity ----
    bool valid = false;
    if (tid < nc) {
        int o = (int)(v & 0xFFFFFFFFULL);
        float4 b = d_boxes[o];
        sb[tid] = b;
        sa[tid] = (b.z - b.x) * (b.w - b.y);
        valid = (__uint_as_float(~(unsigned)(v >> 32)) >= CONF_T);
    }
    unsigned vb = __ballot_sync(0xFFFFFFFFu, valid);
    if (lane == 0) validw_s[w] = vb;
    if (tid == 0) { d_ccnt[c] = 0; changed = 1; }  // self-reset for next graph replay
    __syncthreads();

    // ---- build conflict masks directly in smem (w-major: broadcast reads) ----
    const int npairs = nwords * nc;
    for (int pr = tid; pr < npairs; pr += 1024) {
        int wq = pr / nc;
        int i  = pr - wq * nc;
        int j0 = wq << 5;
        unsigned bits = 0u;
        if (i < j0 + 32) {                     // else structurally zero (still stored)
            float4 bi = sb[i];
            float  ai = sa[i];
#pragma unroll
            for (int u = 0; u < 32; u++) {
                int j = j0 + u;
                float4 bj = sb[j];             // broadcast across lanes
                float xx1 = fmaxf(bi.x, bj.x);
                float yy1 = fmaxf(bi.y, bj.y);
                float xx2 = fminf(bi.z, bj.z);
                float yy2 = fminf(bi.w, bj.w);
                float inter = fmaxf(1e-28f, xx2 - xx1) * fmaxf(1e-28f, yy2 - yy1);
                float denom = ai + sa[j] - inter;
                // iou > 0.5 exactly: denom>0 -> inter>denom/2; denom==0 -> inter>0; denom<0 -> never
                bool conf = (j > i) && (j < nc) && (denom >= 0.f) && (inter > 0.5f * denom);
                bits |= ((unsigned)conf) << u;
            }
        }
        smask[i * SPITCH + wq] = bits;         // lanes: consecutive i -> conflict-free
    }
    if (tid < 32) keep_s[tid] = validw_s[tid]; // K^0 = valid
    __syncthreads();

    // ---- Jacobi fixed-point iteration ----
    const int maxit = 2 * nc + 8;
    for (int it = 0; it < maxit && changed; it++) {
        unsigned acc = 0u;
        if (w < nwords) {
            for (int i = lane; i < nc; i += 32) {
                unsigned kb = 0u - ((keep_s[i >> 5] >> (i & 31)) & 1u);
                acc |= smask[i * SPITCH + w] & kb;  // bank (i+w)%32: conflict-free
            }
        }
#pragma unroll
        for (int d = 16; d; d >>= 1) acc |= __shfl_xor_sync(0xFFFFFFFFu, acc, d);
        if (lane == 0) supp_s[w] = acc;
        __syncthreads();
        if (tid < 32) {                        // warp 0: update + convergence test
            if (tid == 0) changed = 0;
            unsigned nk = validw_s[tid] & ~supp_s[tid];
            unsigned diff = __ballot_sync(0xFFFFFFFFu, nk != keep_s[tid]);
            keep_s[tid] = nk;
            if (tid == 0 && diff) changed = 1;
        }
        __syncthreads();
    }

    // ---- scatter keep flags back to original indices ----
    if (tid < nc) {
        int o = (int)(sk[tid] & 0xFFFFFFFFULL);
        out[6 * N_ANCH + o] = ((keep_s[w] >> lane) & 1u) ? 1.f : 0.f;
    }
}

// ---------------- launch ----------------
extern "C" void kernel_launch(void* const* d_in, const int* in_sizes, int n_in,
                              void* d_out, int out_size)
{
    const float* p0 = (const float*)d_in[0];   // pred_1 (64,75,52,52)
    const float* p1 = (const float*)d_in[1];   // pred_2 (64,75,26,26)
    const float* p2 = (const float*)d_in[2];   // pred_3 (64,75,13,13)
    float* out = (float*)d_out;

    const int smem = CCAP * 8 + CCAP * 16 + CCAP * 4 + CCAP * SPITCH * 4; // 160 KB
    cudaFuncSetAttribute(k_cnms, cudaFuncAttributeMaxDynamicSharedMemorySize, smem);

    k_decode<<<(N_ANCH + 255) / 256, 256>>>(p0, p1, p2, out);
    k_cnms  <<<NCLS, 1024, smem>>>(out);
}

// round 14
// speedup vs baseline: 1.2111x; 1.2111x over previous
#include <cuda_runtime.h>
#include <math.h>

#define N_ANCH 10647
#define OFF1   8112     // 52*52*3
#define OFF2   10140    // OFF1 + 26*26*3
#define HW0    2704     // 52*52
#define HW1    676      // 26*26
#define HW2    169      // 13*13
#define CONF_T 0.001f
#define NCLS   20
#define CCAP   1024     // per-class capacity (mean ~532, sd ~22.5)
#define STRIPS 8

// ---------------- device scratch (static, no allocation) ----------------
__device__ float4             d_boxes[N_ANCH];          // decoded boxes (unclipped, normalized)
__device__ unsigned long long d_ckey [NCLS * CCAP];     // per-class keys (~score<<32 | idx)
__device__ int                d_ccnt [NCLS];            // per-class counts (self-resetting)
__device__ int                d_snc  [NCLS];            // clamped counts
__device__ unsigned long long d_skey [NCLS * CCAP];     // sorted keys
__device__ float4             d_sbox [NCLS * CCAP];     // sorted boxes
__device__ float              d_sarea[NCLS * CCAP];     // sorted areas
__device__ unsigned int       d_validw[NCLS * 32];      // validity bits, packed
__device__ unsigned int       d_masksT[NCLS * 32 * CCAP]; // TRANSPOSED masks: [class][word][row]
__device__ int                d_done [NCLS];            // per-class strip arrival counter

// anchors[scale][a][wh], already multiplied by {4,2,1}
__constant__ float c_anch[3][3][2] = {
    {{ 4.f, 6.f},{ 8.f,12.f},{12.f,10.f}},   // stride 8
    {{ 3.f, 7.f},{ 6.f, 8.f},{ 8.f, 6.f}},   // stride 16
    {{3.5f, 5.f},{ 5.f,4.5f},{ 8.f, 8.f}}    // stride 32
};

__device__ __forceinline__ float sigmoidf_(float v) { return 1.f / (1.f + expf(-v)); }

// ---------------- kernel 1: decode batch 0 + class bucketing (coalesced) ----------------
__global__ void k_decode(const float* __restrict__ p0,
                         const float* __restrict__ p1,
                         const float* __restrict__ p2,
                         float* __restrict__ out)
{
    int t = blockIdx.x * blockDim.x + threadIdx.x;
    if (t >= N_ANCH) return;

    const float* p; int G, HW, off, sc; float st;
    if (t < OFF1)      { p = p0; G = 52; HW = HW0; off = 0;    sc = 0; st =  8.f; }
    else if (t < OFF2) { p = p1; G = 26; HW = HW1; off = OFF1; sc = 1; st = 16.f; }
    else               { p = p2; G = 13; HW = HW2; off = OFF2; sc = 2; st = 32.f; }

    int rel = t - off;
    int a   = rel / HW;
    int hw  = rel - a * HW;
    int y   = hw / G;
    int x   = hw - y * G;
    int GG  = HW;
    int idx = off + hw * 3 + a;                // original anchor index
    const float* base = p + hw;                // batch 0, channel stride = GG

    float obj = sigmoidf_(base[(size_t)a * GG]);

    float l[NCLS];
    float m = -3.4e38f; int am = 0;
#pragma unroll
    for (int c = 0; c < NCLS; c++) {
        l[c] = base[(size_t)(3 + a * NCLS + c) * GG];
        if (l[c] > m) { m = l[c]; am = c; }
    }
    float s = 0.f;
#pragma unroll
    for (int c = 0; c < NCLS; c++) s += expf(l[c] - m);
    float score = obj * (1.f / s);

    float tx = base[(size_t)(63 + a * 4 + 0) * GG];
    float ty = base[(size_t)(63 + a * 4 + 1) * GG];
    float tw = base[(size_t)(63 + a * 4 + 2) * GG];
    float th = base[(size_t)(63 + a * 4 + 3) * GG];

    float cx = sigmoidf_(tx) + (float)x;
    float cy = sigmoidf_(ty) + (float)y;

    float aw, ah;
    if (hw == GG - 1) { aw = 0.f; ah = 0.f; }  // reference zeroes last hw row
    else { aw = c_anch[sc][a][0]; ah = c_anch[sc][a][1]; }

    float bw = expf(tw) * aw;
    float bh = expf(th) * ah;

    float x1 = (cx - bw * 0.5f) * st / 416.f;
    float y1 = (cy - bh * 0.5f) * st / 416.f;
    float x2 = (cx + bw * 0.5f) * st / 416.f;
    float y2 = (cy + bh * 0.5f) * st / 416.f;

    d_boxes[idx] = make_float4(x1, y1, x2, y2);

    unsigned long long key =
        ((unsigned long long)(~__float_as_uint(score)) << 32) | (unsigned)idx;
    int pos = atomicAdd(&d_ccnt[am], 1);
    if (pos < CCAP) d_ckey[am * CCAP + pos] = key;

    float4 ob;
    ob.x = fminf(fmaxf(x1 * 416.f, 0.f), 415.f) / 416.f;
    ob.y = fminf(fmaxf(y1 * 416.f, 0.f), 415.f) / 416.f;
    ob.z = fminf(fmaxf(x2 * 416.f, 0.f), 415.f) / 416.f;
    ob.w = fminf(fmaxf(y2 * 416.f, 0.f), 415.f) / 416.f;
    *(float4*)(out + (size_t)idx * 4) = ob;
    out[4 * N_ANCH + idx] = score;
    out[5 * N_ANCH + idx] = (float)am;
}

// ---------------- kernel 2: hybrid register/shfl bitonic sort + gather ----------------
__global__ void __launch_bounds__(1024) k_sortgather()
{
    __shared__ unsigned long long sx[CCAP];    // exchange buffer for j>=32 steps
    const int c    = blockIdx.x;
    const int tid  = threadIdx.x;
    const int lane = tid & 31;
    const int wrp  = tid >> 5;

    int nc = d_ccnt[c];
    if (nc > CCAP) nc = CCAP;

    unsigned long long v = (tid < nc) ? d_ckey[c * CCAP + tid] : 0xFFFFFFFFFFFFFFFFULL;

    // bitonic: real keys are distinct (idx in low bits) -> min/max comparator safe
    for (int k = 2; k <= CCAP; k <<= 1) {
        int j = k >> 1;
        for (; j >= 32; j >>= 1) {             // cross-warp: smem exchange
            sx[tid] = v;
            __syncthreads();
            unsigned long long o = sx[tid ^ j];
            bool takeMin = (((tid & j) == 0) == ((tid & k) == 0));
            v = takeMin ? (v < o ? v : o) : (v < o ? o : v);
            __syncthreads();
        }
        for (; j > 0; j >>= 1) {               // intra-warp: shfl, no barriers
            unsigned long long o = __shfl_xor_sync(0xFFFFFFFFu, v, j);
            bool takeMin = (((lane & j) == 0) == ((tid & k) == 0));
            v = takeMin ? (v < o ? v : o) : (v < o ? o : v);
        }
    }

    // thread tid now holds rank-tid element
    d_skey[c * CCAP + tid] = v;
    bool valid = false;
    if (tid < nc) {
        int o = (int)(v & 0xFFFFFFFFULL);
        float4 b = d_boxes[o];
        d_sbox [c * CCAP + tid] = b;
        d_sarea[c * CCAP + tid] = (b.z - b.x) * (b.w - b.y);
        valid = (__uint_as_float(~(unsigned)(v >> 32)) >= CONF_T);
    }
    unsigned vb = __ballot_sync(0xFFFFFFFFu, valid);
    if (lane == 0) d_validw[c * 32 + wrp] = vb;
    if (tid == 0) { d_snc[c] = nc; d_ccnt[c] = 0; }   // self-reset for next replay
}

// ---------------- kernel 3: distributed mask build + last-arriver Jacobi sweep ----------------
// Jacobi fixed-point: K^{t+1} = valid & ~supp(K^t), K^0 = valid. Antitone operator;
// masks strictly upper-triangular -> iterates converge exactly to greedy-NMS keep set.
__global__ void __launch_bounds__(256) k_buildsweep(float* __restrict__ out)
{
    __shared__ float4 sb[CCAP];                 // 16 KB
    __shared__ float  sa[CCAP];                 //  4 KB
    __shared__ unsigned int validw_s[32], keep_s[32], supp_s[32];
    __shared__ int last_s, changed;

    const int c    = blockIdx.y;
    const int s    = blockIdx.x;
    const int tid  = threadIdx.x;
    const int lane = tid & 31;
    const int w    = tid >> 5;

    const int nc = d_snc[c];
    const int nwords = (nc + 31) >> 5;

    // ---- build phase (strips with s >= nwords skip work but still arrive) ----
    if (s < nwords) {
        for (int i = tid; i < nc; i += 256) {
            sb[i] = d_sbox [c * CCAP + i];
            sa[i] = d_sarea[c * CCAP + i];
        }
        __syncthreads();

        for (int wq = s; wq < nwords; wq += STRIPS) {
            int j0   = wq << 5;
            int rows = min(nc, j0 + 32);       // rows >= j0+32 structurally zero (never read)
            unsigned int* dst = d_masksT + ((size_t)c * 32 + wq) * CCAP;
            for (int i = tid; i < rows; i += 256) { // lanes: consecutive i, shared wq -> broadcast
                float4 bi = sb[i];
                float  ai = sa[i];
                unsigned bits = 0u;
#pragma unroll
                for (int u = 0; u < 32; u++) {
                    int j = j0 + u;
                    float4 bj = sb[j];         // broadcast across lanes
                    float xx1 = fmaxf(bi.x, bj.x);
                    float yy1 = fmaxf(bi.y, bj.y);
                    float xx2 = fminf(bi.z, bj.z);
                    float yy2 = fminf(bi.w, bj.w);
                    float inter = fmaxf(1e-28f, xx2 - xx1) * fmaxf(1e-28f, yy2 - yy1);
                    float denom = ai + sa[j] - inter;
                    // iou > 0.5 exactly: denom>0 -> inter>denom/2; denom==0 -> inter>0; denom<0 -> never
                    bool conf = (j > i) && (j < nc) && (denom >= 0.f) && (inter > 0.5f * denom);
                    bits |= ((unsigned)conf) << u;
                }
                dst[i] = bits;                 // coalesced (consecutive i)
            }
        }
        __syncthreads();
    }

    // ---- last-arriver handoff (release/acquire via fence + atomic counter) ----
    __threadfence();
    if (tid == 0) last_s = (atomicAdd(&d_done[c], 1) == STRIPS - 1);
    __syncthreads();
    if (!last_s) return;
    __threadfence();                            // acquire: all strips' masks visible
    if (tid == 0) { d_done[c] = 0; changed = 1; } // reset for next graph replay

    // ---- Jacobi sweep (this block only; masks read coalesced from L1/L2) ----
    if (tid < 32) {
        unsigned va = d_validw[c * 32 + tid];
        validw_s[tid] = va;
        keep_s[tid]   = va;                    // K^0 = valid
    }
    __syncthreads();

    const int maxit = 2 * nc + 8;
    for (int it = 0; it < maxit && changed; it++) {
        // warp w computes supp words {w, w+8, w+16, w+24}
#pragma unroll
        for (int q = 0; q < 4; q++) {
            int wq = w + 8 * q;
            int lim = min(nc, (wq << 5) + 32); // build wrote exactly rows [0, lim)
            const unsigned int* rowp = d_masksT + ((size_t)c * 32 + wq) * CCAP;
            unsigned acc = 0u;
            for (int i = lane; i < lim; i += 32) {
                unsigned kb = 0u - ((keep_s[i >> 5] >> (i & 31)) & 1u);
                acc |= rowp[i] & kb;           // coalesced LDG, independent -> MLP-hidden
            }
#pragma unroll
            for (int d = 16; d; d >>= 1) acc |= __shfl_xor_sync(0xFFFFFFFFu, acc, d);
            if (lane == 0) supp_s[wq] = acc;
        }
        __syncthreads();
        if (tid < 32) {                        // warp 0: update + convergence test
            if (tid == 0) changed = 0;
            unsigned nk = validw_s[tid] & ~supp_s[tid];
            unsigned diff = __ballot_sync(0xFFFFFFFFu, nk != keep_s[tid]);
            keep_s[tid] = nk;
            if (tid == 0 && diff) changed = 1;
        }
        __syncthreads();
    }

    // ---- scatter keep flags back to original indices ----
    for (int r = tid; r < nc; r += 256) {
        int o = (int)(d_skey[c * CCAP + r] & 0xFFFFFFFFULL);
        out[6 * N_ANCH + o] = ((keep_s[r >> 5] >> (r & 31)) & 1u) ? 1.f : 0.f;
    }
}

// ---------------- launch ----------------
extern "C" void kernel_launch(void* const* d_in, const int* in_sizes, int n_in,
                              void* d_out, int out_size)
{
    const float* p0 = (const float*)d_in[0];   // pred_1 (64,75,52,52)
    const float* p1 = (const float*)d_in[1];   // pred_2 (64,75,26,26)
    const float* p2 = (const float*)d_in[2];   // pred_3 (64,75,13,13)
    float* out = (float*)d_out;

    k_decode    <<<(N_ANCH + 255) / 256, 256>>>(p0, p1, p2, out);
    k_sortgather<<<NCLS, 1024>>>();
    k_buildsweep<<<dim3(STRIPS, NCLS), 256>>>(out);
}

// round 15
// speedup vs baseline: 1.3683x; 1.1298x over previous
#include <cuda_runtime.h>
#include <math.h>

#define N_ANCH 10647
#define OFF1   8112     // 52*52*3
#define OFF2   10140    // OFF1 + 26*26*3
#define HW0    2704     // 52*52
#define HW1    676      // 26*26
#define HW2    169      // 13*13
#define CONF_T 0.001f
#define NCLS   20
#define CCAP   1024     // per-class capacity (mean ~532, sd ~22.5)
#define STRIPS 8

// ---------------- device scratch (static, no allocation) ----------------
__device__ float4             d_boxes[N_ANCH];          // decoded boxes (unclipped, normalized)
__device__ unsigned long long d_ckey [NCLS * CCAP];     // per-class keys (~score<<32 | idx)
__device__ int                d_ccnt [NCLS];            // per-class counts (self-resetting)
__device__ int                d_snc  [NCLS];            // clamped counts
__device__ unsigned long long d_skey [NCLS * CCAP];     // sorted keys
__device__ float4             d_sbox [NCLS * CCAP];     // sorted boxes
__device__ float              d_sarea[NCLS * CCAP];     // sorted areas
__device__ unsigned int       d_validw[NCLS * 32];      // validity bits, packed
__device__ unsigned int       d_masksT[NCLS * 32 * CCAP]; // TRANSPOSED masks: [class][word][row]

// anchors[scale][a][wh], already multiplied by {4,2,1}
__constant__ float c_anch[3][3][2] = {
    {{ 4.f, 6.f},{ 8.f,12.f},{12.f,10.f}},   // stride 8
    {{ 3.f, 7.f},{ 6.f, 8.f},{ 8.f, 6.f}},   // stride 16
    {{3.5f, 5.f},{ 5.f,4.5f},{ 8.f, 8.f}}    // stride 32
};

__device__ __forceinline__ float sigmoidf_(float v) { return 1.f / (1.f + expf(-v)); }

// ---------------- kernel 1: decode batch 0 + class bucketing (coalesced) ----------------
__global__ void k_decode(const float* __restrict__ p0,
                         const float* __restrict__ p1,
                         const float* __restrict__ p2,
                         float* __restrict__ out)
{
    int t = blockIdx.x * blockDim.x + threadIdx.x;
    if (t >= N_ANCH) return;

    const float* p; int G, HW, off, sc; float st;
    if (t < OFF1)      { p = p0; G = 52; HW = HW0; off = 0;    sc = 0; st =  8.f; }
    else if (t < OFF2) { p = p1; G = 26; HW = HW1; off = OFF1; sc = 1; st = 16.f; }
    else               { p = p2; G = 13; HW = HW2; off = OFF2; sc = 2; st = 32.f; }

    int rel = t - off;
    int a   = rel / HW;
    int hw  = rel - a * HW;
    int y   = hw / G;
    int x   = hw - y * G;
    int GG  = HW;
    int idx = off + hw * 3 + a;                // original anchor index
    const float* base = p + hw;                // batch 0, channel stride = GG

    float obj = sigmoidf_(base[(size_t)a * GG]);

    float l[NCLS];
    float m = -3.4e38f; int am = 0;
#pragma unroll
    for (int c = 0; c < NCLS; c++) {
        l[c] = base[(size_t)(3 + a * NCLS + c) * GG];
        if (l[c] > m) { m = l[c]; am = c; }
    }
    float s = 0.f;
#pragma unroll
    for (int c = 0; c < NCLS; c++) s += expf(l[c] - m);
    float score = obj * (1.f / s);

    float tx = base[(size_t)(63 + a * 4 + 0) * GG];
    float ty = base[(size_t)(63 + a * 4 + 1) * GG];
    float tw = base[(size_t)(63 + a * 4 + 2) * GG];
    float th = base[(size_t)(63 + a * 4 + 3) * GG];

    float cx = sigmoidf_(tx) + (float)x;
    float cy = sigmoidf_(ty) + (float)y;

    float aw, ah;
    if (hw == GG - 1) { aw = 0.f; ah = 0.f; }  // reference zeroes last hw row
    else { aw = c_anch[sc][a][0]; ah = c_anch[sc][a][1]; }

    float bw = expf(tw) * aw;
    float bh = expf(th) * ah;

    float x1 = (cx - bw * 0.5f) * st / 416.f;
    float y1 = (cy - bh * 0.5f) * st / 416.f;
    float x2 = (cx + bw * 0.5f) * st / 416.f;
    float y2 = (cy + bh * 0.5f) * st / 416.f;

    d_boxes[idx] = make_float4(x1, y1, x2, y2);

    unsigned long long key =
        ((unsigned long long)(~__float_as_uint(score)) << 32) | (unsigned)idx;
    int pos = atomicAdd(&d_ccnt[am], 1);
    if (pos < CCAP) d_ckey[am * CCAP + pos] = key;

    float4 ob;
    ob.x = fminf(fmaxf(x1 * 416.f, 0.f), 415.f) / 416.f;
    ob.y = fminf(fmaxf(y1 * 416.f, 0.f), 415.f) / 416.f;
    ob.z = fminf(fmaxf(x2 * 416.f, 0.f), 415.f) / 416.f;
    ob.w = fminf(fmaxf(y2 * 416.f, 0.f), 415.f) / 416.f;
    *(float4*)(out + (size_t)idx * 4) = ob;
    out[4 * N_ANCH + idx] = score;
    out[5 * N_ANCH + idx] = (float)am;
}

// ---------------- kernel 2: hybrid register/shfl bitonic sort + gather ----------------
__global__ void __launch_bounds__(1024) k_sortgather()
{
    __shared__ unsigned long long sx[CCAP];    // exchange buffer for j>=32 steps
    const int c    = blockIdx.x;
    const int tid  = threadIdx.x;
    const int lane = tid & 31;
    const int wrp  = tid >> 5;

    int nc = d_ccnt[c];
    if (nc > CCAP) nc = CCAP;

    unsigned long long v = (tid < nc) ? d_ckey[c * CCAP + tid] : 0xFFFFFFFFFFFFFFFFULL;

    // bitonic: real keys are distinct (idx in low bits) -> min/max comparator safe
    for (int k = 2; k <= CCAP; k <<= 1) {
        int j = k >> 1;
        for (; j >= 32; j >>= 1) {             // cross-warp: smem exchange
            sx[tid] = v;
            __syncthreads();
            unsigned long long o = sx[tid ^ j];
            bool takeMin = (((tid & j) == 0) == ((tid & k) == 0));
            v = takeMin ? (v < o ? v : o) : (v < o ? o : v);
            __syncthreads();
        }
        for (; j > 0; j >>= 1) {               // intra-warp: shfl, no barriers
            unsigned long long o = __shfl_xor_sync(0xFFFFFFFFu, v, j);
            bool takeMin = (((lane & j) == 0) == ((tid & k) == 0));
            v = takeMin ? (v < o ? v : o) : (v < o ? o : v);
        }
    }

    // thread tid now holds rank-tid element
    d_skey[c * CCAP + tid] = v;
    bool valid = false;
    if (tid < nc) {
        int o = (int)(v & 0xFFFFFFFFULL);
        float4 b = d_boxes[o];
        d_sbox [c * CCAP + tid] = b;
        d_sarea[c * CCAP + tid] = (b.z - b.x) * (b.w - b.y);
        valid = (__uint_as_float(~(unsigned)(v >> 32)) >= CONF_T);
    }
    unsigned vb = __ballot_sync(0xFFFFFFFFu, valid);
    if (lane == 0) d_validw[c * 32 + wrp] = vb;
    if (tid == 0) { d_snc[c] = nc; d_ccnt[c] = 0; }   // self-reset for next replay
}

// ---------------- kernel 3: distributed mask build (8 strips x 20 classes) ----------------
__global__ void __launch_bounds__(256) k_build()
{
    __shared__ float4 sb[CCAP];                 // 16 KB
    __shared__ float  sa[CCAP];                 //  4 KB
    const int c   = blockIdx.y;
    const int s   = blockIdx.x;
    const int tid = threadIdx.x;

    const int nc = d_snc[c];
    const int nwords = (nc + 31) >> 5;
    if (s >= nwords) return;

    for (int i = tid; i < nc; i += 256) {
        sb[i] = d_sbox [c * CCAP + i];
        sa[i] = d_sarea[c * CCAP + i];
    }
    __syncthreads();

    for (int wq = s; wq < nwords; wq += STRIPS) {
        int j0   = wq << 5;
        int rows = min(nc, j0 + 32);           // rows >= j0+32 structurally zero (zero-filled by sweep)
        unsigned int* dst = d_masksT + ((size_t)c * 32 + wq) * CCAP;
        for (int i = tid; i < rows; i += 256) { // lanes: consecutive i, shared wq -> broadcast reads
            float4 bi = sb[i];
            float  ai = sa[i];
            unsigned bits = 0u;
#pragma unroll
            for (int u = 0; u < 32; u++) {
                int j = j0 + u;
                float4 bj = sb[j];             // broadcast across lanes
                float xx1 = fmaxf(bi.x, bj.x);
                float yy1 = fmaxf(bi.y, bj.y);
                float xx2 = fminf(bi.z, bj.z);
                float yy2 = fminf(bi.w, bj.w);
                float inter = fmaxf(1e-28f, xx2 - xx1) * fmaxf(1e-28f, yy2 - yy1);
                float denom = ai + sa[j] - inter;
                // iou > 0.5 exactly: denom>0 -> inter>denom/2; denom==0 -> inter>0; denom<0 -> never
                bool conf = (j > i) && (j < nc) && (denom >= 0.f) && (inter > 0.5f * denom);
                bits |= ((unsigned)conf) << u;
            }
            dst[i] = bits;                     // coalesced (consecutive i)
        }
    }
}

// ---------------- kernel 4: full-row smem-staged Jacobi sweep + scatter ----------------
// Jacobi fixed-point: K^{t+1} = valid & ~supp(K^t), K^0 = valid. Antitone operator;
// masks strictly upper-triangular -> iterates converge exactly to greedy-NMS keep set.
__global__ void __launch_bounds__(1024) k_sweep(float* __restrict__ out)
{
    extern __shared__ unsigned int sm[];       // nwords * ncr words (worst 128 KB)
    __shared__ unsigned int validw_s[32], keep_s[32], supp_s[32];
    __shared__ int changed;

    const int c    = blockIdx.x;
    const int tid  = threadIdx.x;
    const int lane = tid & 31;
    const int w    = tid >> 5;                 // warp id == word this warp owns in Jacobi
    const int nc   = d_snc[c];
    const int nwords = (nc + 31) >> 5;
    const int ncr  = (nc + 31) & ~31;          // row-padded pitch

    if (tid < 32) {
        unsigned va = d_validw[c * 32 + tid];
        validw_s[tid] = va;
        keep_s[tid]   = va;                    // K^0 = valid
    }
    if (tid == 0) changed = 1;

    // stage mask region: sm[wq*ncr + i]; zero-fill rows build never wrote (i >= lim)
    const int total = nwords * ncr;
    for (int t = tid; t < total; t += 1024) {
        int wq = t / ncr;                      // ncr is 32-multiple; small loop (~12 iters)
        int i  = t - wq * ncr;
        int lim = min(nc, (wq << 5) + 32);
        sm[t] = (i < lim) ? d_masksT[((size_t)c * 32 + wq) * CCAP + i] : 0u;
    }
    __syncthreads();

    // Jacobi fixed-point; warp w computes supp word w (w < nwords <= 32)
    const int maxit = 2 * nc + 8;
    for (int it = 0; it < maxit && changed; it++) {
        unsigned acc = 0u;
        if (w < nwords) {
            const unsigned int* rowp = sm + w * ncr;
            for (int i = lane; i < nc; i += 32) {
                unsigned kb = 0u - ((keep_s[i >> 5] >> (i & 31)) & 1u);
                acc |= rowp[i] & kb;           // bank = i mod 32: conflict-free, pipelined
            }
        }
#pragma unroll
        for (int d = 16; d; d >>= 1) acc |= __shfl_xor_sync(0xFFFFFFFFu, acc, d);
        if (lane == 0) supp_s[w] = acc;
        __syncthreads();
        if (tid < 32) {                        // warp 0: update + convergence test
            if (tid == 0) changed = 0;
            unsigned nk = validw_s[tid] & ~supp_s[tid];
            unsigned diff = __ballot_sync(0xFFFFFFFFu, nk != keep_s[tid]);
            keep_s[tid] = nk;
            if (tid == 0 && diff) changed = 1;
        }
        __syncthreads();
    }

    // scatter keep flags back to original indices
    if (tid < nc) {
        int o = (int)(d_skey[c * CCAP + tid] & 0xFFFFFFFFULL);
        out[6 * N_ANCH + o] = ((keep_s[w] >> lane) & 1u) ? 1.f : 0.f;
    }
}

// ---------------- launch ----------------
extern "C" void kernel_launch(void* const* d_in, const int* in_sizes, int n_in,
                              void* d_out, int out_size)
{
    const float* p0 = (const float*)d_in[0];   // pred_1 (64,75,52,52)
    const float* p1 = (const float*)d_in[1];   // pred_2 (64,75,26,26)
    const float* p2 = (const float*)d_in[2];   // pred_3 (64,75,13,13)
    float* out = (float*)d_out;

    const int sweep_smem = 32 * CCAP * 4;      // worst-case 128 KB
    cudaFuncSetAttribute(k_sweep, cudaFuncAttributeMaxDynamicSharedMemorySize, sweep_smem);

    k_decode    <<<(N_ANCH + 255) / 256, 256>>>(p0, p1, p2, out);
    k_sortgather<<<NCLS, 1024>>>();
    k_build     <<<dim3(STRIPS, NCLS), 256>>>();
    k_sweep     <<<NCLS, 1024, sweep_smem>>>(out);
}